// round 2
// baseline (speedup 1.0000x reference)
#include <cuda_runtime.h>
#include <math.h>

#define N_NODES 84
#define P_PAIRS 3486
#define HSZ     2048
#define H2      1024
#define H3      (3 * HSZ)   /* 6144 */
#define LN_EPS  1e-5f

// ---------------------------------------------------------------------------
// Scratch (static __device__ arrays; no allocation anywhere)
// ---------------------------------------------------------------------------
__device__ float  g_G [N_NODES * H3];    // per-node GRU input gates  [84, 6144]
__device__ float  g_GH[P_PAIRS * H3];    // hidden-side gates         [3486, 6144]
__device__ float  g_H [P_PAIRS * HSZ];   // GRU hidden state          [3486, 2048]
__device__ float  g_A1[P_PAIRS * HSZ];   // layer-1 activations       [3486, 2048]
__device__ float  g_A2[P_PAIRS * H2];    // layer-2 activations       [3486, 1024]
__device__ float  g_A3[P_PAIRS * H2];    // layer-3 activations       [3486, 1024]
__device__ float  g_vals[P_PAIRS];
__device__ int    g_iu[P_PAIRS];
__device__ int    g_ju[P_PAIRS];
__device__ double g_red[6];              // 3 LN slots x (sum, sumsq)

// ---------------------------------------------------------------------------
// Init: pair indices + zero LN accumulators (re-run every launch -> graph-safe)
// ---------------------------------------------------------------------------
__global__ void init_kernel() {
    int idx = blockIdx.x * blockDim.x + threadIdx.x;
    if (idx < 6) g_red[idx] = 0.0;
    if (idx < P_PAIRS) {
        int i = 0, rem = idx;
        while (rem >= N_NODES - 1 - i) { rem -= N_NODES - 1 - i; i++; }
        g_iu[idx] = i;
        g_ju[idx] = i + 1 + rem;
    }
}

// ---------------------------------------------------------------------------
// SGEMM (NT): C[M,Nc] = A[M,K] @ B[Nc,K]^T + bias[Nc], optional ReLU.
// 128x128x8 tile, 256 threads, 8x8 per-thread micro-tile.
// K must be a multiple of 8 (all call sites: 2048/1024/64).
// ---------------------------------------------------------------------------
__global__ __launch_bounds__(256, 2)
void sgemm_nt(const float* __restrict__ A, const float* __restrict__ B,
              const float* __restrict__ bias, float* __restrict__ C,
              int M, int Nc, int K, int do_relu)
{
    __shared__ float As[8][128];
    __shared__ float Bs[8][128];

    const int tid   = threadIdx.x;
    const int ldrow = tid >> 1;          // 0..127
    const int ldcol = (tid & 1) << 2;    // 0 or 4
    const int tx    = tid & 15;
    const int ty    = tid >> 4;
    const int row0  = blockIdx.y * 128;
    const int col0  = blockIdx.x * 128;

    float acc[8][8];
#pragma unroll
    for (int i = 0; i < 8; i++)
#pragma unroll
        for (int j = 0; j < 8; j++) acc[i][j] = 0.f;

    const int ar = row0 + ldrow;
    const int br = col0 + ldrow;

    for (int k0 = 0; k0 < K; k0 += 8) {
        float4 av = make_float4(0.f, 0.f, 0.f, 0.f);
        float4 bv = make_float4(0.f, 0.f, 0.f, 0.f);
        if (ar < M)  av = *reinterpret_cast<const float4*>(A + (size_t)ar * K + k0 + ldcol);
        if (br < Nc) bv = *reinterpret_cast<const float4*>(B + (size_t)br * K + k0 + ldcol);

        __syncthreads();   // protect previous iteration's smem reads
        As[ldcol + 0][ldrow] = av.x;  As[ldcol + 1][ldrow] = av.y;
        As[ldcol + 2][ldrow] = av.z;  As[ldcol + 3][ldrow] = av.w;
        Bs[ldcol + 0][ldrow] = bv.x;  Bs[ldcol + 1][ldrow] = bv.y;
        Bs[ldcol + 2][ldrow] = bv.z;  Bs[ldcol + 3][ldrow] = bv.w;
        __syncthreads();

#pragma unroll
        for (int kk = 0; kk < 8; kk++) {
            float a[8], b[8];
#pragma unroll
            for (int i = 0; i < 8; i++) a[i] = As[kk][ty * 8 + i];
#pragma unroll
            for (int j = 0; j < 8; j++) b[j] = Bs[kk][tx * 8 + j];
#pragma unroll
            for (int i = 0; i < 8; i++)
#pragma unroll
                for (int j = 0; j < 8; j++)
                    acc[i][j] = fmaf(a[i], b[j], acc[i][j]);
        }
    }

#pragma unroll
    for (int i = 0; i < 8; i++) {
        const int row = row0 + ty * 8 + i;
        if (row >= M) continue;
#pragma unroll
        for (int j = 0; j < 8; j++) {
            const int col = col0 + tx * 8 + j;
            if (col >= Nc) continue;
            float v = acc[i][j] + bias[col];
            if (do_relu) v = fmaxf(v, 0.f);
            C[(size_t)row * Nc + col] = v;
        }
    }
}

// ---------------------------------------------------------------------------
// Fused GRU gate combine. gi is gathered from the per-node table g_G via
// iu (stage 1) or ju (stage 2); gh comes from g_GH.
// h_out = (1-z)*tanh(i_n + r*h_n) + z*h_prev
// ---------------------------------------------------------------------------
__global__ void gru_combine(const float* __restrict__ hprev,
                            float* __restrict__ hout, int use_ju)
{
    long idx = (long)blockIdx.x * blockDim.x + threadIdx.x;
    if (idx >= (long)P_PAIRS * HSZ) return;
    const int p = (int)(idx / HSZ);
    const int j = (int)(idx - (long)p * HSZ);
    const int node = use_ju ? g_ju[p] : g_iu[p];

    const float* gi = g_G  + (size_t)node * H3;
    const float* gh = g_GH + (size_t)p    * H3;

    const float r = 1.f / (1.f + expf(-(gi[j]           + gh[j])));
    const float z = 1.f / (1.f + expf(-(gi[j + HSZ]     + gh[j + HSZ])));
    const float n = tanhf(gi[j + 2 * HSZ] + r * gh[j + 2 * HSZ]);
    const float hp = hprev[idx];
    hout[idx] = (1.f - z) * n + z * hp;
}

// ---------------------------------------------------------------------------
// Full-tensor LayerNorm: two passes (reduce, then normalize in place).
// ---------------------------------------------------------------------------
__global__ void ln_reduce(const float* __restrict__ x, long n, int slot)
{
    __shared__ float ss[256], ss2[256];
    float s = 0.f, s2 = 0.f;
    for (long i = (long)blockIdx.x * blockDim.x + threadIdx.x; i < n;
         i += (long)gridDim.x * blockDim.x) {
        const float v = x[i];
        s += v; s2 += v * v;
    }
    ss[threadIdx.x] = s; ss2[threadIdx.x] = s2;
    __syncthreads();
    for (int st = 128; st > 0; st >>= 1) {
        if (threadIdx.x < st) {
            ss[threadIdx.x]  += ss[threadIdx.x + st];
            ss2[threadIdx.x] += ss2[threadIdx.x + st];
        }
        __syncthreads();
    }
    if (threadIdx.x == 0) {
        atomicAdd(&g_red[slot * 2 + 0], (double)ss[0]);
        atomicAdd(&g_red[slot * 2 + 1], (double)ss2[0]);
    }
}

__global__ void ln_norm(float* __restrict__ x,
                        const float* __restrict__ w, const float* __restrict__ b,
                        long n, int slot)
{
    long idx = (long)blockIdx.x * blockDim.x + threadIdx.x;
    if (idx >= n) return;
    const double s  = g_red[slot * 2 + 0];
    const double s2 = g_red[slot * 2 + 1];
    const double mu = s / (double)n;
    const double var = s2 / (double)n - mu * mu;
    const float inv = rsqrtf((float)var + LN_EPS);
    const float fmu = (float)mu;
    x[idx] = (x[idx] - fmu) * inv * w[idx] + b[idx];
}

// ---------------------------------------------------------------------------
// Final projection: one warp per pair; vals[p] = sigmoid(dot(A3[p], W4) + b4)
// ---------------------------------------------------------------------------
__global__ void final_dot(const float* __restrict__ W4, const float* __restrict__ b4)
{
    const int warp = (blockIdx.x * blockDim.x + threadIdx.x) >> 5;
    const int lane = threadIdx.x & 31;
    if (warp >= P_PAIRS) return;
    const float* xr = g_A3 + (size_t)warp * H2;
    float s = 0.f;
    for (int k = lane; k < H2; k += 32) s += xr[k] * W4[k];
#pragma unroll
    for (int off = 16; off; off >>= 1) s += __shfl_down_sync(0xffffffffu, s, off);
    if (lane == 0) g_vals[warp] = 1.f / (1.f + expf(-(s + b4[0])));
}

// ---------------------------------------------------------------------------
// Symmetric scatter into the 84x84 output (also zeroes the diagonal).
// ---------------------------------------------------------------------------
__global__ void scatter_out(float* __restrict__ out)
{
    const int idx = blockIdx.x * blockDim.x + threadIdx.x;
    if (idx >= N_NODES * N_NODES) return;
    const int i = idx / N_NODES, j = idx % N_NODES;
    if (i == j) { out[idx] = 0.f; return; }
    const int a = i < j ? i : j;
    const int b = i < j ? j : i;
    const int p = a * (N_NODES - 1) - (a * (a - 1)) / 2 + (b - a - 1);
    out[idx] = g_vals[p];
}

// ---------------------------------------------------------------------------
// Launch
// ---------------------------------------------------------------------------
extern "C" void kernel_launch(void* const* d_in, const int* in_sizes, int n_in,
                              void* d_out, int out_size)
{
    const float* x       = (const float*)d_in[0];
    const float* hid     = (const float*)d_in[1];
    const float* gru_Wih = (const float*)d_in[2];
    const float* gru_Whh = (const float*)d_in[3];
    const float* gru_bih = (const float*)d_in[4];
    const float* gru_bhh = (const float*)d_in[5];
    const float* W1      = (const float*)d_in[6];
    const float* b1      = (const float*)d_in[7];
    const float* ln1_w   = (const float*)d_in[8];
    const float* ln1_b   = (const float*)d_in[9];
    const float* W2      = (const float*)d_in[10];
    const float* b2      = (const float*)d_in[11];
    const float* ln2_w   = (const float*)d_in[12];
    const float* ln2_b   = (const float*)d_in[13];
    const float* W3      = (const float*)d_in[14];
    const float* b3      = (const float*)d_in[15];
    const float* ln3_w   = (const float*)d_in[16];
    const float* ln3_b   = (const float*)d_in[17];
    const float* W4      = (const float*)d_in[18];
    const float* b4      = (const float*)d_in[19];
    float* out           = (float*)d_out;

    float *pG, *pGH, *pH, *pA1, *pA2, *pA3;
    cudaGetSymbolAddress((void**)&pG,  g_G);
    cudaGetSymbolAddress((void**)&pGH, g_GH);
    cudaGetSymbolAddress((void**)&pH,  g_H);
    cudaGetSymbolAddress((void**)&pA1, g_A1);
    cudaGetSymbolAddress((void**)&pA2, g_A2);
    cudaGetSymbolAddress((void**)&pA3, g_A3);

    const long PH  = (long)P_PAIRS * HSZ;   // 7,139,328
    const long PH2 = (long)P_PAIRS * H2;    // 3,569,664
    const int  EW  = 256;

    init_kernel<<<(P_PAIRS + 255) / 256, 256>>>();

    // Per-node input gates: G = x @ Wih^T + bih   [84, 6144]
    sgemm_nt<<<dim3(H3 / 128, 1), 256>>>(x, gru_Wih, gru_bih, pG, N_NODES, H3, 64, 0);

    // GRU step 1
    sgemm_nt<<<dim3(H3 / 128, 28), 256>>>(hid, gru_Whh, gru_bhh, pGH, P_PAIRS, H3, HSZ, 0);
    gru_combine<<<(unsigned)((PH + EW - 1) / EW), EW>>>(hid, pH, 0);

    // GRU step 2
    sgemm_nt<<<dim3(H3 / 128, 28), 256>>>(pH, gru_Whh, gru_bhh, pGH, P_PAIRS, H3, HSZ, 0);
    gru_combine<<<(unsigned)((PH + EW - 1) / EW), EW>>>(pH, pH, 1);

    // Layer 1: relu(H @ W1^T + b1) -> full LN
    sgemm_nt<<<dim3(HSZ / 128, 28), 256>>>(pH, W1, b1, pA1, P_PAIRS, HSZ, HSZ, 1);
    ln_reduce<<<1024, 256>>>(pA1, PH, 0);
    ln_norm<<<(unsigned)((PH + EW - 1) / EW), EW>>>(pA1, ln1_w, ln1_b, PH, 0);

    // Layer 2
    sgemm_nt<<<dim3(H2 / 128, 28), 256>>>(pA1, W2, b2, pA2, P_PAIRS, H2, HSZ, 1);
    ln_reduce<<<1024, 256>>>(pA2, PH2, 1);
    ln_norm<<<(unsigned)((PH2 + EW - 1) / EW), EW>>>(pA2, ln2_w, ln2_b, PH2, 1);

    // Layer 3
    sgemm_nt<<<dim3(H2 / 128, 28), 256>>>(pA2, W3, b3, pA3, P_PAIRS, H2, H2, 1);
    ln_reduce<<<1024, 256>>>(pA3, PH2, 2);
    ln_norm<<<(unsigned)((PH2 + EW - 1) / EW), EW>>>(pA3, ln3_w, ln3_b, PH2, 2);

    // Final sigmoid projection + symmetric scatter
    final_dot<<<(P_PAIRS * 32 + 255) / 256, 256>>>(W4, b4);
    scatter_out<<<(N_NODES * N_NODES + 255) / 256, 256>>>(out);
}

// round 8
// speedup vs baseline: 5.7754x; 5.7754x over previous
#include <cuda_runtime.h>
#include <cuda_fp16.h>
#include <math.h>
#include <stdint.h>

#define N_NODES 84
#define P_PAIRS 3486
#define P_PAD   3584          /* 28 * 128 */
#define HSZ     2048
#define H2      1024
#define H3      (3 * HSZ)     /* 6144 */
#define LN_EPS  1e-5f

// ---------------------------------------------------------------------------
// Scratch (static __device__; zero-initialized at module load)
// ---------------------------------------------------------------------------
__device__ float  g_G  [128 * H3];        // per-node input gates (f32), row-padded
__device__ float  g_GH [P_PAIRS * H3];
__device__ float  g_A1 [P_PAIRS * HSZ];
__device__ float  g_A2 [P_PAIRS * H2];
__device__ float  g_A3 [P_PAIRS * H2];
__device__ float  g_vals[P_PAIRS];
__device__ int    g_iu[P_PAIRS];
__device__ int    g_ju[P_PAIRS];
__device__ double g_red[6];

// fp16 operands; activation buffers padded to P_PAD rows (padding stays zero)
__device__ __half g_hX  [128 * 64];
__device__ __half g_hWih[H3 * 64];
__device__ __half g_hWhh[(size_t)H3 * HSZ];
__device__ __half g_hW1 [(size_t)HSZ * HSZ];
__device__ __half g_hW2 [(size_t)H2 * HSZ];
__device__ __half g_hW3 [(size_t)H2 * H2];
__device__ __half g_hHid[(size_t)P_PAD * HSZ];
__device__ __half g_hH  [(size_t)P_PAD * HSZ];
__device__ __half g_hA1 [(size_t)P_PAD * HSZ];
__device__ __half g_hA2 [(size_t)P_PAD * H2];
__device__ __half g_hA3 [(size_t)P_PAD * H2];

// ---------------------------------------------------------------------------
// PTX helpers (family-generic: cp.async / ldmatrix / mma.sync only)
// ---------------------------------------------------------------------------
__device__ __forceinline__ uint32_t smem_u32(const void* p) {
    uint32_t a;
    asm("{ .reg .u64 t; cvta.to.shared.u64 t, %1; cvt.u32.u64 %0, t; }" : "=r"(a) : "l"(p));
    return a;
}
__device__ __forceinline__ void cp16(uint32_t dst, const void* src) {
    asm volatile("cp.async.cg.shared.global [%0], [%1], 16;" :: "r"(dst), "l"(src) : "memory");
}
__device__ __forceinline__ void cp_commit() { asm volatile("cp.async.commit_group;" ::: "memory"); }
__device__ __forceinline__ void cp_wait0()  { asm volatile("cp.async.wait_group 0;" ::: "memory"); }
__device__ __forceinline__ void cp_wait1()  { asm volatile("cp.async.wait_group 1;" ::: "memory"); }

__device__ __forceinline__ void ldsm4(uint32_t& r0, uint32_t& r1, uint32_t& r2, uint32_t& r3,
                                      uint32_t addr) {
    asm volatile("ldmatrix.sync.aligned.m8n8.x4.shared.b16 {%0,%1,%2,%3}, [%4];"
                 : "=r"(r0), "=r"(r1), "=r"(r2), "=r"(r3) : "r"(addr));
}
__device__ __forceinline__ void mma16816(float* c, const uint32_t* a, const uint32_t* b) {
    asm volatile("mma.sync.aligned.m16n8k16.row.col.f32.f16.f16.f32 "
                 "{%0,%1,%2,%3}, {%4,%5,%6,%7}, {%8,%9}, {%0,%1,%2,%3};"
                 : "+f"(c[0]), "+f"(c[1]), "+f"(c[2]), "+f"(c[3])
                 : "r"(a[0]), "r"(a[1]), "r"(a[2]), "r"(a[3]), "r"(b[0]), "r"(b[1]));
}

#define SW128(o) ((o) ^ ((((uint32_t)(o)) >> 3) & 0x70))

// ---------------------------------------------------------------------------
// HMMA GEMM (NT): C[M,Nc] = A[M,K]@B[Nc,K]^T + bias, optional relu + LN stats.
// 128x128 CTA tile, BK=64, fp16 in / fp32 accum, double-buffered cp.async.
// 8 warps: warp_m = wid&3 (32 rows), warp_n = wid>>2 (64 cols).
// ---------------------------------------------------------------------------
__global__ __launch_bounds__(256)
void gemm_tc(const __half* __restrict__ A, const __half* __restrict__ B,
             const float* __restrict__ bias, float* __restrict__ C,
             int Mvalid, int Nc, int K, int do_relu, int stats_slot)
{
    extern __shared__ char smem[];
    const uint32_t sb = smem_u32(smem);
    const int tid    = threadIdx.x;
    const int wid    = tid >> 5;
    const int lane   = tid & 31;
    const int warp_m = wid & 3;
    const int warp_n = wid >> 2;
    const int row0   = blockIdx.y * 128;
    const int col0   = blockIdx.x * 128;

    float acc[2][8][4];
#pragma unroll
    for (int i = 0; i < 2; i++)
#pragma unroll
        for (int j = 0; j < 8; j++)
#pragma unroll
            for (int q = 0; q < 4; q++) acc[i][j][q] = 0.f;

    const int S = K >> 6;   // 64-wide K slabs

    // prefetch slab 0 into buffer 0
    {
#pragma unroll
        for (int i = 0; i < 4; i++) {
            const int c = tid + (i << 8);
            const int r = c >> 3, cq = c & 7;
            const uint32_t so = SW128(((uint32_t)r << 7) + ((uint32_t)cq << 4));
            cp16(sb + so,         A + (size_t)(row0 + r) * K + (cq << 3));
            cp16(sb + 32768 + so, B + (size_t)(col0 + r) * K + (cq << 3));
        }
        cp_commit();
    }

    for (int s = 0; s < S; s++) {
        if (s + 1 < S) {
            const uint32_t off = ((s + 1) & 1) ? 16384u : 0u;
            const int k0 = (s + 1) << 6;
#pragma unroll
            for (int i = 0; i < 4; i++) {
                const int c = tid + (i << 8);
                const int r = c >> 3, cq = c & 7;
                const uint32_t so = SW128(((uint32_t)r << 7) + ((uint32_t)cq << 4));
                cp16(sb + off + so,         A + (size_t)(row0 + r) * K + k0 + (cq << 3));
                cp16(sb + 32768 + off + so, B + (size_t)(col0 + r) * K + k0 + (cq << 3));
            }
            cp_commit();
            cp_wait1();
        } else {
            cp_wait0();
        }
        __syncthreads();

        const uint32_t sA = sb + ((s & 1) ? 16384u : 0u);
        const uint32_t sB = sA + 32768u;

#pragma unroll
        for (int kk = 0; kk < 4; kk++) {
            uint32_t aF[2][4];
#pragma unroll
            for (int mi = 0; mi < 2; mi++) {
                const int arow = warp_m * 32 + mi * 16 + (lane & 15);
                const uint32_t boff = (uint32_t)kk * 32 + ((lane >> 4) << 4);
                ldsm4(aF[mi][0], aF[mi][1], aF[mi][2], aF[mi][3],
                      sA + SW128(((uint32_t)arow << 7) + boff));
            }
#pragma unroll
            for (int nj = 0; nj < 4; nj++) {
                uint32_t bF[4];
                const int brow = warp_n * 64 + nj * 16 + ((lane >> 4) << 3) + (lane & 7);
                const uint32_t boff = (uint32_t)kk * 32 + (((lane >> 3) & 1) << 4);
                ldsm4(bF[0], bF[1], bF[2], bF[3],
                      sB + SW128(((uint32_t)brow << 7) + boff));
#pragma unroll
                for (int mi = 0; mi < 2; mi++) {
                    mma16816(acc[mi][nj * 2 + 0], aF[mi], bF);
                    mma16816(acc[mi][nj * 2 + 1], aF[mi], bF + 2);
                }
            }
        }
        __syncthreads();
    }

    // Epilogue: bias + relu + store + (optional) LN partial stats
    float s_sum = 0.f, s_sq = 0.f;
#pragma unroll
    for (int mi = 0; mi < 2; mi++) {
        const int rbase = row0 + warp_m * 32 + mi * 16 + (lane >> 2);
#pragma unroll
        for (int half = 0; half < 2; half++) {
            const int r = rbase + half * 8;
            if (r >= Mvalid) continue;
#pragma unroll
            for (int nt = 0; nt < 8; nt++) {
                const int c0 = col0 + warp_n * 64 + nt * 8 + (lane & 3) * 2;
                float v0 = acc[mi][nt][half * 2 + 0] + bias[c0];
                float v1 = acc[mi][nt][half * 2 + 1] + bias[c0 + 1];
                if (do_relu) { v0 = fmaxf(v0, 0.f); v1 = fmaxf(v1, 0.f); }
                if (stats_slot >= 0) { s_sum += v0 + v1; s_sq += v0 * v0 + v1 * v1; }
                *reinterpret_cast<float2*>(C + (size_t)r * Nc + c0) = make_float2(v0, v1);
            }
        }
    }

    if (stats_slot >= 0) {
#pragma unroll
        for (int off = 16; off; off >>= 1) {
            s_sum += __shfl_xor_sync(0xffffffffu, s_sum, off);
            s_sq  += __shfl_xor_sync(0xffffffffu, s_sq,  off);
        }
        float* red = reinterpret_cast<float*>(smem);
        __syncthreads();                       // smem tiles no longer needed
        if (lane == 0) { red[wid] = s_sum; red[8 + wid] = s_sq; }
        __syncthreads();
        if (tid == 0) {
            float t1 = 0.f, t2 = 0.f;
#pragma unroll
            for (int w = 0; w < 8; w++) { t1 += red[w]; t2 += red[8 + w]; }
            atomicAdd(&g_red[stats_slot * 2 + 0], (double)t1);
            atomicAdd(&g_red[stats_slot * 2 + 1], (double)t2);
        }
    }
}

// ---------------------------------------------------------------------------
// Elementwise kernels
// ---------------------------------------------------------------------------
__global__ void init_kernel() {
    int idx = blockIdx.x * blockDim.x + threadIdx.x;
    if (idx < 6) g_red[idx] = 0.0;
    if (idx < P_PAIRS) {
        int i = 0, rem = idx;
        while (rem >= N_NODES - 1 - i) { rem -= N_NODES - 1 - i; i++; }
        g_iu[idx] = i;
        g_ju[idx] = i + 1 + rem;
    }
}

__global__ void f32_to_f16(const float* __restrict__ in, __half* __restrict__ out, long n) {
    for (long i = (long)blockIdx.x * blockDim.x + threadIdx.x; i < n;
         i += (long)gridDim.x * blockDim.x)
        out[i] = __float2half(in[i]);
}

__global__ void gru_combine(const float* __restrict__ hprev_f32,
                            const __half* __restrict__ hprev_f16,
                            __half* __restrict__ hout, int use_ju)
{
    long idx = (long)blockIdx.x * blockDim.x + threadIdx.x;
    if (idx >= (long)P_PAIRS * HSZ) return;
    const int p = (int)(idx / HSZ);
    const int j = (int)(idx - (long)p * HSZ);
    const int node = use_ju ? g_ju[p] : g_iu[p];

    const float* gi = g_G  + (size_t)node * H3;
    const float* gh = g_GH + (size_t)p    * H3;

    const float r = 1.f / (1.f + expf(-(gi[j]           + gh[j])));
    const float z = 1.f / (1.f + expf(-(gi[j + HSZ]     + gh[j + HSZ])));
    const float n = tanhf(gi[j + 2 * HSZ] + r * gh[j + 2 * HSZ]);
    const float hp = hprev_f32 ? hprev_f32[idx]
                               : __half2float(hprev_f16[(size_t)p * HSZ + j]);
    hout[(size_t)p * HSZ + j] = __float2half((1.f - z) * n + z * hp);
}

__global__ void ln_norm_h(const float* __restrict__ x, const float* __restrict__ w,
                          const float* __restrict__ b, __half* __restrict__ out,
                          long n, int slot)
{
    long idx = (long)blockIdx.x * blockDim.x + threadIdx.x;
    if (idx >= n) return;
    const double s  = g_red[slot * 2 + 0];
    const double s2 = g_red[slot * 2 + 1];
    const double mu = s / (double)n;
    const double var = s2 / (double)n - mu * mu;
    const float inv = rsqrtf((float)var + LN_EPS);
    const float fmu = (float)mu;
    const float v = (x[idx] - fmu) * inv * w[idx] + b[idx];
    out[idx] = __float2half(v);
}

__global__ void final_dot(const __half* __restrict__ h3,
                          const float* __restrict__ W4, const float* __restrict__ b4)
{
    const int warp = (blockIdx.x * blockDim.x + threadIdx.x) >> 5;
    const int lane = threadIdx.x & 31;
    if (warp >= P_PAIRS) return;
    const __half* xr = h3 + (size_t)warp * H2;
    float s = 0.f;
    for (int k = lane; k < H2; k += 32) s += __half2float(xr[k]) * W4[k];
#pragma unroll
    for (int off = 16; off; off >>= 1) s += __shfl_down_sync(0xffffffffu, s, off);
    if (lane == 0) g_vals[warp] = 1.f / (1.f + expf(-(s + b4[0])));
}

__global__ void scatter_out(float* __restrict__ out)
{
    const int idx = blockIdx.x * blockDim.x + threadIdx.x;
    if (idx >= N_NODES * N_NODES) return;
    const int i = idx / N_NODES, j = idx % N_NODES;
    if (i == j) { out[idx] = 0.f; return; }
    const int a = i < j ? i : j;
    const int b = i < j ? j : i;
    const int p = a * (N_NODES - 1) - (a * (a - 1)) / 2 + (b - a - 1);
    out[idx] = g_vals[p];
}

// ---------------------------------------------------------------------------
// Launch
// ---------------------------------------------------------------------------
extern "C" void kernel_launch(void* const* d_in, const int* in_sizes, int n_in,
                              void* d_out, int out_size)
{
    const float* x       = (const float*)d_in[0];
    const float* hid     = (const float*)d_in[1];
    const float* gru_Wih = (const float*)d_in[2];
    const float* gru_Whh = (const float*)d_in[3];
    const float* gru_bih = (const float*)d_in[4];
    const float* gru_bhh = (const float*)d_in[5];
    const float* W1      = (const float*)d_in[6];
    const float* b1      = (const float*)d_in[7];
    const float* ln1_w   = (const float*)d_in[8];
    const float* ln1_b   = (const float*)d_in[9];
    const float* W2      = (const float*)d_in[10];
    const float* b2      = (const float*)d_in[11];
    const float* ln2_w   = (const float*)d_in[12];
    const float* ln2_b   = (const float*)d_in[13];
    const float* W3      = (const float*)d_in[14];
    const float* b3      = (const float*)d_in[15];
    const float* ln3_w   = (const float*)d_in[16];
    const float* ln3_b   = (const float*)d_in[17];
    const float* W4      = (const float*)d_in[18];
    const float* b4      = (const float*)d_in[19];
    float* out           = (float*)d_out;

    float *pG, *pGH, *pA1, *pA2, *pA3;
    __half *hX, *hWih, *hWhh, *hW1, *hW2, *hW3, *hHid, *hH, *hA1, *hA2, *hA3;
    cudaGetSymbolAddress((void**)&pG,   g_G);
    cudaGetSymbolAddress((void**)&pGH,  g_GH);
    cudaGetSymbolAddress((void**)&pA1,  g_A1);
    cudaGetSymbolAddress((void**)&pA2,  g_A2);
    cudaGetSymbolAddress((void**)&pA3,  g_A3);
    cudaGetSymbolAddress((void**)&hX,   g_hX);
    cudaGetSymbolAddress((void**)&hWih, g_hWih);
    cudaGetSymbolAddress((void**)&hWhh, g_hWhh);
    cudaGetSymbolAddress((void**)&hW1,  g_hW1);
    cudaGetSymbolAddress((void**)&hW2,  g_hW2);
    cudaGetSymbolAddress((void**)&hW3,  g_hW3);
    cudaGetSymbolAddress((void**)&hHid, g_hHid);
    cudaGetSymbolAddress((void**)&hH,   g_hH);
    cudaGetSymbolAddress((void**)&hA1,  g_hA1);
    cudaGetSymbolAddress((void**)&hA2,  g_hA2);
    cudaGetSymbolAddress((void**)&hA3,  g_hA3);

    static int smem_set = 0;
    const int SMEM_BYTES = 65536;
    if (!smem_set) {
        cudaFuncSetAttribute(gemm_tc, cudaFuncAttributeMaxDynamicSharedMemorySize, SMEM_BYTES);
        smem_set = 1;
    }

    const long PH  = (long)P_PAIRS * HSZ;
    const long PH2 = (long)P_PAIRS * H2;
    const int  EW  = 256;

    init_kernel<<<(P_PAIRS + 255) / 256, 256>>>();

    // fp16 conversions (memory-bound, ~30us total)
    f32_to_f16<<<64, 256>>>(x,        hX,   (long)N_NODES * 64);
    f32_to_f16<<<256, 256>>>(gru_Wih, hWih, (long)H3 * 64);
    f32_to_f16<<<2048, 256>>>(gru_Whh, hWhh, (long)H3 * HSZ);
    f32_to_f16<<<1024, 256>>>(W1,      hW1,  (long)HSZ * HSZ);
    f32_to_f16<<<512, 256>>>(W2,       hW2,  (long)H2 * HSZ);
    f32_to_f16<<<512, 256>>>(W3,       hW3,  (long)H2 * H2);
    f32_to_f16<<<2048, 256>>>(hid,     hHid, PH);

    // GEMM0: per-node input gates  G = x @ Wih^T + bih   [84, 6144], K=64
    gemm_tc<<<dim3(H3 / 128, 1), 256, SMEM_BYTES>>>(hX, hWih, gru_bih, pG,
                                                    N_NODES, H3, 64, 0, -1);
    // GRU step 1
    gemm_tc<<<dim3(H3 / 128, P_PAD / 128), 256, SMEM_BYTES>>>(hHid, hWhh, gru_bhh, pGH,
                                                              P_PAIRS, H3, HSZ, 0, -1);
    gru_combine<<<(unsigned)((PH + EW - 1) / EW), EW>>>(hid, nullptr, hH, 0);

    // GRU step 2
    gemm_tc<<<dim3(H3 / 128, P_PAD / 128), 256, SMEM_BYTES>>>(hH, hWhh, gru_bhh, pGH,
                                                              P_PAIRS, H3, HSZ, 0, -1);
    gru_combine<<<(unsigned)((PH + EW - 1) / EW), EW>>>(nullptr, hH, hH, 1);

    // Layer 1: relu(H @ W1^T + b1), fused LN stats
    gemm_tc<<<dim3(HSZ / 128, P_PAD / 128), 256, SMEM_BYTES>>>(hH, hW1, b1, pA1,
                                                               P_PAIRS, HSZ, HSZ, 1, 0);
    ln_norm_h<<<(unsigned)((PH + EW - 1) / EW), EW>>>(pA1, ln1_w, ln1_b, hA1, PH, 0);

    // Layer 2
    gemm_tc<<<dim3(H2 / 128, P_PAD / 128), 256, SMEM_BYTES>>>(hA1, hW2, b2, pA2,
                                                              P_PAIRS, H2, HSZ, 1, 1);
    ln_norm_h<<<(unsigned)((PH2 + EW - 1) / EW), EW>>>(pA2, ln2_w, ln2_b, hA2, PH2, 1);

    // Layer 3
    gemm_tc<<<dim3(H2 / 128, P_PAD / 128), 256, SMEM_BYTES>>>(hA2, hW3, b3, pA3,
                                                              P_PAIRS, H2, H2, 1, 2);
    ln_norm_h<<<(unsigned)((PH2 + EW - 1) / EW), EW>>>(pA3, ln3_w, ln3_b, hA3, PH2, 2);

    // Final sigmoid projection + symmetric scatter
    final_dot<<<(P_PAIRS * 32 + 255) / 256, 256>>>(hA3, W4, b4);
    scatter_out<<<(N_NODES * N_NODES + 255) / 256, 256>>>(out);
}